// round 1
// baseline (speedup 1.0000x reference)
#include <cuda_runtime.h>
#include <cuda_bf16.h>
#include <math.h>

// Problem constants
#define NNODE 650
#define FDIM  512
#define NE    150000          // raw edges
#define ET    150650          // edges + self loops

// ---------------- device scratch (no allocations allowed) ----------------
__device__ float g_x[NNODE * FDIM];    // node features (input / layer output)
__device__ float g_h[NNODE * FDIM];    // h = x @ W
__device__ float g_als[NNODE];         // per-node source attention logit
__device__ float g_ald[NNODE];         // per-node dest attention logit
__device__ int   g_deg[NNODE];
__device__ int   g_off[NNODE + 1];
__device__ int   g_cur[NNODE];
__device__ int   g_csr_src[ET];

// ---------------- small helpers ----------------
__device__ __forceinline__ void edge_sd(int i, const int* __restrict__ ei, int& s, int& d) {
    if (i < NE) { s = ei[i]; d = ei[NE + i]; }
    else        { s = i - NE; d = i - NE; }
}

// ---------------- kernels ----------------

// concat x_s (400 rows) and x_t (250 rows) into g_x
__global__ void concat_kernel(const float* __restrict__ xs, const float* __restrict__ xt) {
    int i = blockIdx.x * 256 + threadIdx.x;
    if (i < NNODE * FDIM) {
        g_x[i] = (i < 400 * FDIM) ? xs[i] : xt[i - 400 * FDIM];
    }
}

__global__ void zero_deg_kernel() {
    int i = blockIdx.x * 256 + threadIdx.x;
    if (i < NNODE) g_deg[i] = 0;
}

__global__ void count_deg_kernel(const int* __restrict__ ei) {
    int i = blockIdx.x * 256 + threadIdx.x;
    if (i >= ET) return;
    int s, d; edge_sd(i, ei, s, d);
    atomicAdd(&g_deg[d], 1);
}

// single-block Hillis-Steele inclusive scan over 650 degrees
__global__ void scan_kernel() {
    __shared__ int a[1024];
    int t = threadIdx.x;
    a[t] = (t < NNODE) ? g_deg[t] : 0;
    __syncthreads();
    for (int o = 1; o < 1024; o <<= 1) {
        int v = (t >= o) ? a[t - o] : 0;
        __syncthreads();
        a[t] += v;
        __syncthreads();
    }
    if (t < NNODE) {
        g_off[t + 1] = a[t];
        g_cur[t]     = a[t] - g_deg[t];   // exclusive
    }
    if (t == 0) g_off[0] = 0;
}

__global__ void fill_csr_kernel(const int* __restrict__ ei) {
    int i = blockIdx.x * 256 + threadIdx.x;
    if (i >= ET) return;
    int s, d; edge_sd(i, ei, s, d);
    int p = atomicAdd(&g_cur[d], 1);
    g_csr_src[p] = s;
}

// C[650x512] = g_x[650x512] @ B[512x512]   (writes g_h)
// BM=32, BN=64, BK=32, 256 threads, 2x4 microtile
__global__ __launch_bounds__(256) void gemm_kernel(const float* __restrict__ B) {
    __shared__ float As[32][33];     // As[k][m]
    __shared__ float Bs[32][64];     // Bs[k][n]
    const int tid = threadIdx.x;
    const int bm = blockIdx.y * 32;
    const int bn = blockIdx.x * 64;
    const int tr = tid >> 4;         // 0..15
    const int tc = tid & 15;         // 0..15
    const int arow = tid >> 3;       // 0..31
    const int acol = (tid & 7) * 4;  // 0..28
    const int brow = tid >> 4;       // 0..15
    const int bcol = (tid & 15) * 4; // 0..60

    float acc[2][4] = {{0.f,0.f,0.f,0.f},{0.f,0.f,0.f,0.f}};

    for (int k0 = 0; k0 < FDIM; k0 += 32) {
        float4 av = make_float4(0.f, 0.f, 0.f, 0.f);
        int gr = bm + arow;
        if (gr < NNODE)
            av = *(const float4*)(&g_x[gr * FDIM + k0 + acol]);
        As[acol + 0][arow] = av.x;
        As[acol + 1][arow] = av.y;
        As[acol + 2][arow] = av.z;
        As[acol + 3][arow] = av.w;

        float4 bv0 = *(const float4*)(B + (k0 + brow)      * FDIM + bn + bcol);
        float4 bv1 = *(const float4*)(B + (k0 + brow + 16) * FDIM + bn + bcol);
        *(float4*)&Bs[brow][bcol]      = bv0;
        *(float4*)&Bs[brow + 16][bcol] = bv1;
        __syncthreads();

#pragma unroll
        for (int k = 0; k < 32; k++) {
            float a0 = As[k][tr * 2 + 0];
            float a1 = As[k][tr * 2 + 1];
            float4 b = *(const float4*)&Bs[k][tc * 4];
            acc[0][0] += a0 * b.x; acc[0][1] += a0 * b.y;
            acc[0][2] += a0 * b.z; acc[0][3] += a0 * b.w;
            acc[1][0] += a1 * b.x; acc[1][1] += a1 * b.y;
            acc[1][2] += a1 * b.z; acc[1][3] += a1 * b.w;
        }
        __syncthreads();
    }

    int r0 = bm + tr * 2;
    if (r0 < NNODE)
        *(float4*)(&g_h[r0 * FDIM + bn + tc * 4]) =
            make_float4(acc[0][0], acc[0][1], acc[0][2], acc[0][3]);
    if (r0 + 1 < NNODE)
        *(float4*)(&g_h[(r0 + 1) * FDIM + bn + tc * 4]) =
            make_float4(acc[1][0], acc[1][1], acc[1][2], acc[1][3]);
}

// per-node attention logits: g_als[n] = h[n].a_src, g_ald[n] = h[n].a_dst
__global__ __launch_bounds__(256) void logits_kernel(const float* __restrict__ av,
                                                     const float* __restrict__ dv) {
    int n = blockIdx.x;
    int t = threadIdx.x;
    float s1 = 0.f, s2 = 0.f;
    for (int f = t; f < FDIM; f += 256) {
        float h = g_h[n * FDIM + f];
        s1 += h * av[f];
        s2 += h * dv[f];
    }
    __shared__ float r1[256], r2[256];
    r1[t] = s1; r2[t] = s2;
    __syncthreads();
    for (int s = 128; s > 0; s >>= 1) {
        if (t < s) { r1[t] += r1[t + s]; r2[t] += r2[t + s]; }
        __syncthreads();
    }
    if (t == 0) { g_als[n] = r1[0]; g_ald[n] = r2[0]; }
}

// one block per destination node: segment softmax + weighted aggregation
// act: 0 = relu, 1 = leaky_relu(0.01)
__global__ __launch_bounds__(512) void attn_agg_kernel(const float* __restrict__ bias, int act) {
    const int d = blockIdx.x;
    const int t = threadIdx.x;                // feature owned by this thread
    const int beg = g_off[d], end = g_off[d + 1];
    const float aldd = g_ald[d];

    __shared__ float red[512];
    __shared__ float alpha_sh[512];
    __shared__ int   src_sh[512];

    // pass 1: segment max of leaky_relu(als[src] + ald[d], 0.2)
    float mx = -1e30f;
    for (int i = beg + t; i < end; i += 512) {
        float e = g_als[g_csr_src[i]] + aldd;
        e = e > 0.f ? e : 0.2f * e;
        mx = fmaxf(mx, e);
    }
    red[t] = mx;
    __syncthreads();
    for (int s = 256; s > 0; s >>= 1) {
        if (t < s) red[t] = fmaxf(red[t], red[t + s]);
        __syncthreads();
    }
    mx = red[0];
    __syncthreads();

    // pass 2: sum of exp(e - mx)
    float sm = 0.f;
    for (int i = beg + t; i < end; i += 512) {
        float e = g_als[g_csr_src[i]] + aldd;
        e = e > 0.f ? e : 0.2f * e;
        sm += expf(e - mx);
    }
    red[t] = sm;
    __syncthreads();
    for (int s = 256; s > 0; s >>= 1) {
        if (t < s) red[t] += red[t + s];
        __syncthreads();
    }
    float inv = 1.f / (red[0] + 1e-16f);
    __syncthreads();

    // pass 3: acc[f] = sum_i alpha_i * h[src_i][f], chunked through shared mem
    float acc = 0.f;
    for (int base = beg; base < end; base += 512) {
        int n = min(512, end - base);
        if (t < n) {
            int s_ = g_csr_src[base + t];
            src_sh[t] = s_;
            float e = g_als[s_] + aldd;
            e = e > 0.f ? e : 0.2f * e;
            alpha_sh[t] = expf(e - mx) * inv;
        }
        __syncthreads();
#pragma unroll 4
        for (int i = 0; i < n; i++) {
            acc += alpha_sh[i] * g_h[src_sh[i] * FDIM + t];
        }
        __syncthreads();
    }

    float v = acc + bias[t];
    v = (act == 0) ? fmaxf(v, 0.f) : (v > 0.f ? v : 0.01f * v);
    g_x[d * FDIM + t] = v;
}

// fc: out[j] = sigmoid( dot(yflat[j*650 .. j*650+649], fc_w) + fc_b )
__global__ __launch_bounds__(256) void fc_kernel(const float* __restrict__ fcw,
                                                 const float* __restrict__ fcb,
                                                 float* __restrict__ out) {
    int j = blockIdx.x;   // 0..511
    int t = threadIdx.x;
    float acc = 0.f;
    const float* y = &g_x[j * NNODE];   // flat view: [512, 650]
    for (int k = t; k < NNODE; k += 256)
        acc += y[k] * fcw[k];
    __shared__ float r[256];
    r[t] = acc;
    __syncthreads();
    for (int s = 128; s > 0; s >>= 1) {
        if (t < s) r[t] += r[t + s];
        __syncthreads();
    }
    if (t == 0) {
        float v = r[0] + fcb[0];
        out[j] = 1.f / (1.f + expf(-v));
    }
}

// ---------------- launch ----------------
extern "C" void kernel_launch(void* const* d_in, const int* in_sizes, int n_in,
                              void* d_out, int out_size) {
    const float* x_s  = (const float*)d_in[0];
    const float* x_t  = (const float*)d_in[1];
    const int*   ei   = (const int*)  d_in[2];
    // d_in[3] distances, d_in[4] batch : unused (edge_dim=None)
    const float* W1   = (const float*)d_in[5];
    const float* as1  = (const float*)d_in[6];
    const float* ad1  = (const float*)d_in[7];
    const float* b1   = (const float*)d_in[8];
    const float* W4   = (const float*)d_in[9];
    const float* as4  = (const float*)d_in[10];
    const float* ad4  = (const float*)d_in[11];
    const float* b4   = (const float*)d_in[12];
    const float* fcw  = (const float*)d_in[13];
    const float* fcb  = (const float*)d_in[14];
    float* out = (float*)d_out;

    // build node features
    concat_kernel<<<(NNODE * FDIM + 255) / 256, 256>>>(x_s, x_t);

    // build CSR (same for both layers)
    zero_deg_kernel<<<(NNODE + 255) / 256, 256>>>();
    count_deg_kernel<<<(ET + 255) / 256, 256>>>(ei);
    scan_kernel<<<1, 1024>>>();
    fill_csr_kernel<<<(ET + 255) / 256, 256>>>(ei);

    dim3 ggrid(FDIM / 64, (NNODE + 31) / 32);   // 8 x 21

    // layer 1
    gemm_kernel<<<ggrid, 256>>>(W1);
    logits_kernel<<<NNODE, 256>>>(as1, ad1);
    attn_agg_kernel<<<NNODE, 512>>>(b1, 0);     // relu

    // layer 2
    gemm_kernel<<<ggrid, 256>>>(W4);
    logits_kernel<<<NNODE, 256>>>(as4, ad4);
    attn_agg_kernel<<<NNODE, 512>>>(b4, 1);     // leaky 0.01

    // fc + sigmoid
    fc_kernel<<<FDIM, 256>>>(fcw, fcb, out);
}